// round 13
// baseline (speedup 1.0000x reference)
#include <cuda_runtime.h>
#include <cuda_fp16.h>
#include <climits>

#define MAX_NODES 100000
#define MAX_EDGES 3200000
#define CHANNELS  64
#define CAP       64            // per-node segment capacity; overflow path is
                                // exact regardless of degree distribution
#define HBLOCKS   2048          // edge-work blocks in the fused build kernel

// Static scratch (runtime allocation forbidden). All zero-initialized at load
// except g_row_min; every launch restores this state before it ends, so graph
// replays see identical initial conditions.
__device__ __half g_Wth[(size_t)MAX_NODES * CHANNELS];   // 12.8 MB fp16 weights
__device__ int    g_counts[MAX_NODES];                   // zeroed by gather
__device__ int    g_csr[(size_t)MAX_NODES * CAP];        // 25.6 MB padded segments
__device__ int    g_ovf_row[MAX_EDGES];                  // overflow (robustness)
__device__ int    g_ovf_col[MAX_EDGES];
__device__ int    g_ovf_cnt;                             // reset by fixup
__device__ int    g_row_min = INT_MAX;                   // reset by fixup

// ---------------------------------------------------------------------------
// 1) FUSED build: blocks [0, HBLOCKS) bin edges (8 per thread per iteration,
//    atomics front-batched for MLP) + row-min + per-block dtype sniff.
//    Blocks >= HBLOCKS transpose W [64, N] -> g_Wth [N, 64] fp16.
// ---------------------------------------------------------------------------
__device__ __forceinline__ void bin_batch8(const int* r, const int* c) {
    int rank[8];
    #pragma unroll
    for (int k = 0; k < 8; k++)                       // 8 independent ATOMGs
        rank[k] = atomicAdd(&g_counts[r[k]], 1);
    #pragma unroll
    for (int k = 0; k < 8; k++) {                     // 8 batched stores
        if (rank[k] < CAP) {
            g_csr[(size_t)r[k] * CAP + rank[k]] = c[k];
        } else {                                      // cold robustness path
            int o = atomicAdd(&g_ovf_cnt, 1);
            g_ovf_row[o] = r[k];
            g_ovf_col[o] = c[k];
        }
    }
}

__device__ __forceinline__ void bin_one(int r, int c) {
    int rank = atomicAdd(&g_counts[r], 1);
    if (rank < CAP) {
        g_csr[(size_t)r * CAP + rank] = c;
    } else {
        int o = atomicAdd(&g_ovf_cnt, 1);
        g_ovf_row[o] = r;
        g_ovf_col[o] = c;
    }
}

__global__ void __launch_bounds__(256) build_kernel(const float* __restrict__ W,
                                                    const void* __restrict__ edge,
                                                    int N, int E) {
    __shared__ float tile[64][33];
    if (blockIdx.x >= HBLOCKS) {
        // ---- transpose role ----
        int n0 = (blockIdx.x - HBLOCKS) * 32;
        int tx = threadIdx.x & 31, ty = threadIdx.x >> 5;
        #pragma unroll
        for (int j = 0; j < 64; j += 8)
            tile[j + ty][tx] = W[(size_t)(j + ty) * N + n0 + tx];
        __syncthreads();
        #pragma unroll
        for (int j = 0; j < 32; j += 8) {
            int n = j + ty;
            int c = tx * 2;
            __half2 h = __floats2half2_rn(tile[c][n], tile[c + 1][n]);
            *reinterpret_cast<__half2*>(g_Wth + (size_t)(n0 + n) * CHANNELS + c) = h;
        }
        return;
    }

    // ---- per-block dtype sniff: int64 buffers have all-zero odd words for
    //      values < 2^31; 256 random int32 indices are never all zero. ----
    const int* words = (const int*)edge;
    int w = 2 * threadIdx.x + 1;
    int nonzero = (w < 2 * E && words[w] != 0) ? 1 : 0;
    const int is64 = __syncthreads_or(nonzero) ? 0 : 1;

    // ---- edge-binning + min role: 8 edges per thread per iteration ----
    int tid = blockIdx.x * blockDim.x + threadIdx.x;
    int nth = HBLOCKS * blockDim.x;
    int v = INT_MAX;
    int r[8], c[8];
    if (is64) {
        const longlong2* pr = (const longlong2*)edge;
        const longlong2* pc = (const longlong2*)((const long long*)edge + E);
        int ngrp = E >> 3;                       // groups of 8 edges
        for (int i = tid; i < ngrp; i += nth) {
            #pragma unroll
            for (int q = 0; q < 4; q++) {
                longlong2 rr = __ldcs(&pr[4 * i + q]);
                longlong2 cc = __ldcs(&pc[4 * i + q]);
                r[2 * q] = (int)rr.x; r[2 * q + 1] = (int)rr.y;
                c[2 * q] = (int)cc.x; c[2 * q + 1] = (int)cc.y;
            }
            #pragma unroll
            for (int k = 0; k < 8; k++) v = min(v, r[k]);
            bin_batch8(r, c);
        }
        for (int i = (ngrp << 3) + tid; i < E; i += nth) {
            int rr = (int)__ldcs(&((const long long*)edge)[i]);
            int cc = (int)__ldcs(&((const long long*)edge)[(long long)E + i]);
            v = min(v, rr);
            bin_one(rr, cc);
        }
    } else {
        const int4* pr = (const int4*)edge;
        const int4* pc = (const int4*)((const int*)edge + E);
        int ngrp = E >> 3;                       // groups of 8 edges
        for (int i = tid; i < ngrp; i += nth) {
            int4 r0 = __ldcs(&pr[2 * i]);
            int4 r1 = __ldcs(&pr[2 * i + 1]);
            int4 c0 = __ldcs(&pc[2 * i]);
            int4 c1 = __ldcs(&pc[2 * i + 1]);
            r[0] = r0.x; r[1] = r0.y; r[2] = r0.z; r[3] = r0.w;
            r[4] = r1.x; r[5] = r1.y; r[6] = r1.z; r[7] = r1.w;
            c[0] = c0.x; c[1] = c0.y; c[2] = c0.z; c[3] = c0.w;
            c[4] = c1.x; c[5] = c1.y; c[6] = c1.z; c[7] = c1.w;
            #pragma unroll
            for (int k = 0; k < 8; k++) v = min(v, r[k]);
            bin_batch8(r, c);
        }
        for (int i = (ngrp << 3) + tid; i < E; i += nth) {
            int rr = __ldcs(&((const int*)edge)[i]);
            int cc = __ldcs(&((const int*)edge)[E + i]);
            v = min(v, rr);
            bin_one(rr, cc);
        }
    }
    #pragma unroll
    for (int o = 16; o; o >>= 1)
        v = min(v, __shfl_xor_sync(0xffffffffu, v, o));
    if ((threadIdx.x & 31) == 0)
        atomicMin(&g_row_min, v);
}

// ---------------------------------------------------------------------------
// 2) gather: one warp per node; 8 lanes per edge (LDG.128 fp16 W row),
//    4 edges x unroll 4 in flight; streaming out store; resets its node's
//    count afterwards (restores build precondition for the next replay).
// ---------------------------------------------------------------------------
__global__ void __launch_bounds__(256) gather_kernel(const float* __restrict__ b,
                                                     float* __restrict__ out, int N) {
    int warp = (blockIdx.x * blockDim.x + threadIdx.x) >> 5;
    if (warp >= N) return;
    int lane = threadIdx.x & 31;
    int grp  = lane >> 3;
    int sub  = lane & 7;

    int raw = warp + g_row_min;
    int deg = 0;
    const int* seg = g_csr;
    bool valid = (raw < MAX_NODES);
    if (valid) {
        deg = min(g_counts[raw], CAP);
        seg = g_csr + (size_t)raw * CAP;
    }

    float acc[8] = {0.f, 0.f, 0.f, 0.f, 0.f, 0.f, 0.f, 0.f};
    #pragma unroll 4
    for (int j = grp; j < deg; j += 4) {
        int c = __ldg(&seg[j]);
        uint4 w = __ldcg(reinterpret_cast<const uint4*>(g_Wth + (size_t)c * CHANNELS) + sub);
        const __half2* h = reinterpret_cast<const __half2*>(&w);
        #pragma unroll
        for (int k = 0; k < 4; k++) {
            float2 f = __half22float2(h[k]);
            acc[2 * k]     += f.x;
            acc[2 * k + 1] += f.y;
        }
    }
    // restore the zero-counts precondition for the next launch/replay
    if (valid && lane == 0) g_counts[raw] = 0;

    #pragma unroll
    for (int k = 0; k < 8; k++) {
        acc[k] += __shfl_down_sync(0xffffffffu, acc[k], 16);
        acc[k] += __shfl_down_sync(0xffffffffu, acc[k], 8);
    }
    if (grp == 0) {
        float4 b0 = __ldg(reinterpret_cast<const float4*>(b) + sub * 2);
        float4 b1 = __ldg(reinterpret_cast<const float4*>(b) + sub * 2 + 1);
        float4 o0 = make_float4(acc[0] + b0.x, acc[1] + b0.y, acc[2] + b0.z, acc[3] + b0.w);
        float4 o1 = make_float4(acc[4] + b1.x, acc[5] + b1.y, acc[6] + b1.z, acc[7] + b1.w);
        float4* dst = reinterpret_cast<float4*>(out + (size_t)warp * CHANNELS);
        __stcs(dst + sub * 2,     o0);
        __stcs(dst + sub * 2 + 1, o1);
    }
}

// ---------------------------------------------------------------------------
// 3) fixup (single block): fold overflow edges into out via vector reductions
//    (zero iterations on this dataset), then reset global state for the next
//    replay.
// ---------------------------------------------------------------------------
__global__ void fixup_kernel(float* __restrict__ out) {
    const int cnt  = g_ovf_cnt;
    const int rmin = g_row_min;
    long long total = (long long)cnt * 16;
    for (long long t = threadIdx.x; t < total; t += blockDim.x) {
        int e   = (int)(t >> 4);
        int sub = (int)(t & 15);
        int r = g_ovf_row[e] - rmin;
        int c = g_ovf_col[e];
        uint2 w = *reinterpret_cast<const uint2*>(g_Wth + (size_t)c * CHANNELS + sub * 4);
        float2 f0 = __half22float2(*reinterpret_cast<__half2*>(&w.x));
        float2 f1 = __half22float2(*reinterpret_cast<__half2*>(&w.y));
        float* dst = out + (size_t)r * CHANNELS + sub * 4;
        asm volatile("red.global.add.v4.f32 [%0], {%1, %2, %3, %4};"
                     :: "l"(dst), "f"(f0.x), "f"(f0.y), "f"(f1.x), "f"(f1.y)
                     : "memory");
    }
    __syncthreads();
    if (threadIdx.x == 0) {
        g_ovf_cnt = 0;
        g_row_min = INT_MAX;
    }
}

// ---------------------------------------------------------------------------
extern "C" void kernel_launch(void* const* d_in, const int* in_sizes, int n_in,
                              void* d_out, int out_size) {
    const void*  edge = d_in[0];
    const float* W    = (const float*)d_in[1];
    const float* b    = (const float*)d_in[2];
    float*       out  = (float*)d_out;

    const int E = in_sizes[0] / 2;
    const int C = in_sizes[2];             // 64
    const int N = in_sizes[1] / C;         // 100000

    // fused single-pass binning (+min, +dtype sniff) + W transpose
    build_kernel<<<HBLOCKS + N / 32, 256>>>(W, edge, N, E);

    {   // gather: one warp per node (also resets counts)
        long long threads = (long long)N * 32;
        int blocks = (int)((threads + 255) / 256);
        gather_kernel<<<blocks, 256>>>(b, out, N);
    }

    fixup_kernel<<<1, 512>>>(out);   // overflow fold + state reset
}

// round 14
// speedup vs baseline: 1.0023x; 1.0023x over previous
#include <cuda_runtime.h>
#include <cuda_fp16.h>
#include <climits>

#define MAX_NODES 100000
#define MAX_EDGES 3200000
#define CHANNELS  64
#define CAP       64            // per-node segment capacity; overflow path is
                                // exact regardless of degree distribution
#define HBLOCKS   2048          // edge-work blocks in the fused build kernel

// Static scratch (runtime allocation forbidden). All zero-initialized at load
// except g_row_min; every launch restores this state before it ends, so graph
// replays see identical initial conditions.
__device__ __half g_Wth[(size_t)MAX_NODES * CHANNELS];   // 12.8 MB fp16 weights
__device__ int    g_counts[MAX_NODES];                   // zeroed by gather
__device__ int    g_csr[(size_t)MAX_NODES * CAP];        // 25.6 MB padded segments
__device__ int    g_ovf_row[MAX_EDGES];                  // overflow (robustness)
__device__ int    g_ovf_col[MAX_EDGES];
__device__ int    g_ovf_cnt;                             // reset by fixup
__device__ int    g_row_min = INT_MAX;                   // reset by fixup

// ---------------------------------------------------------------------------
// 1) FUSED build, roles INTERLEAVED across the grid so edge-binning blocks
//    and transpose blocks co-reside on every SM (true overlap: transpose's
//    DRAM reads hide under edge-role atomic latency).
//    Edge role: single-pass binning (rank = atomicAdd, store col) + row-min +
//    per-block dtype sniff. Transpose role: W [64, N] -> g_Wth [N, 64] fp16.
// ---------------------------------------------------------------------------
__device__ __forceinline__ void bin_edge(int r, int c) {
    int rank = atomicAdd(&g_counts[r], 1);
    if (rank < CAP) {
        g_csr[(size_t)r * CAP + rank] = c;
    } else {                                  // cold robustness path
        int o = atomicAdd(&g_ovf_cnt, 1);
        g_ovf_row[o] = r;
        g_ovf_col[o] = c;
    }
}

__global__ void __launch_bounds__(256) build_kernel(const float* __restrict__ W,
                                                    const void* __restrict__ edge,
                                                    int N, int E) {
    __shared__ float tile[64][33];
    const int G  = gridDim.x;
    const int bx = blockIdx.x;
    // exact interleave: HBLOCKS edge blocks spread evenly over G blocks
    const long long lo = (long long)bx * HBLOCKS / G;
    const long long hi = (long long)(bx + 1) * HBLOCKS / G;
    const bool is_edge_block = (hi > lo);

    if (!is_edge_block) {
        // ---- transpose role: consecutive ids 0..G-HBLOCKS-1 ----
        int tb = bx - (int)hi;
        int n0 = tb * 32;
        int tx = threadIdx.x & 31, ty = threadIdx.x >> 5;
        #pragma unroll
        for (int j = 0; j < 64; j += 8)
            tile[j + ty][tx] = W[(size_t)(j + ty) * N + n0 + tx];
        __syncthreads();
        #pragma unroll
        for (int j = 0; j < 32; j += 8) {
            int n = j + ty;
            int c = tx * 2;
            __half2 h = __floats2half2_rn(tile[c][n], tile[c + 1][n]);
            *reinterpret_cast<__half2*>(g_Wth + (size_t)(n0 + n) * CHANNELS + c) = h;
        }
        return;
    }

    // ---- per-block dtype sniff: int64 buffers have all-zero odd words for
    //      values < 2^31; 256 random int32 indices are never all zero. ----
    const int* words = (const int*)edge;
    int w = 2 * threadIdx.x + 1;
    int nonzero = (w < 2 * E && words[w] != 0) ? 1 : 0;
    const int is64 = __syncthreads_or(nonzero) ? 0 : 1;

    // ---- edge-binning + min role (edge-block id = lo) ----
    int tid = (int)lo * blockDim.x + threadIdx.x;
    int nth = HBLOCKS * blockDim.x;
    int v = INT_MAX;
    if (is64) {
        const longlong2* pr = (const longlong2*)edge;
        const longlong2* pc = (const longlong2*)((const long long*)edge + E);
        int nchunk = E >> 1;
        for (int i = tid; i < nchunk; i += nth) {
            longlong2 r = __ldcs(&pr[i]);
            longlong2 c = __ldcs(&pc[i]);
            int r0 = (int)r.x, r1 = (int)r.y;
            v = min(v, min(r0, r1));
            bin_edge(r0, (int)c.x);
            bin_edge(r1, (int)c.y);
        }
        for (int i = (nchunk << 1) + tid; i < E; i += nth) {
            int r = (int)__ldcs(&((const long long*)edge)[i]);
            int c = (int)__ldcs(&((const long long*)edge)[(long long)E + i]);
            v = min(v, r);
            bin_edge(r, c);
        }
    } else {
        const int4* pr = (const int4*)edge;
        const int4* pc = (const int4*)((const int*)edge + E);
        int nchunk = E >> 2;
        for (int i = tid; i < nchunk; i += nth) {
            int4 r = __ldcs(&pr[i]);
            int4 c = __ldcs(&pc[i]);
            v = min(v, min(min(r.x, r.y), min(r.z, r.w)));
            bin_edge(r.x, c.x);
            bin_edge(r.y, c.y);
            bin_edge(r.z, c.z);
            bin_edge(r.w, c.w);
        }
        for (int i = (nchunk << 2) + tid; i < E; i += nth) {
            int r = __ldcs(&((const int*)edge)[i]);
            int c = __ldcs(&((const int*)edge)[E + i]);
            v = min(v, r);
            bin_edge(r, c);
        }
    }
    #pragma unroll
    for (int o = 16; o; o >>= 1)
        v = min(v, __shfl_xor_sync(0xffffffffu, v, o));
    if ((threadIdx.x & 31) == 0)
        atomicMin(&g_row_min, v);
}

// ---------------------------------------------------------------------------
// 2) gather: one warp per node; 8 lanes per edge (LDG.128 fp16 W row),
//    4 edges x unroll 4 in flight; streaming out store; resets its node's
//    count afterwards (restores build precondition for the next replay).
// ---------------------------------------------------------------------------
__global__ void __launch_bounds__(256) gather_kernel(const float* __restrict__ b,
                                                     float* __restrict__ out, int N) {
    int warp = (blockIdx.x * blockDim.x + threadIdx.x) >> 5;
    if (warp >= N) return;
    int lane = threadIdx.x & 31;
    int grp  = lane >> 3;
    int sub  = lane & 7;

    int raw = warp + g_row_min;
    int deg = 0;
    const int* seg = g_csr;
    bool valid = (raw < MAX_NODES);
    if (valid) {
        deg = min(g_counts[raw], CAP);
        seg = g_csr + (size_t)raw * CAP;
    }

    float acc[8] = {0.f, 0.f, 0.f, 0.f, 0.f, 0.f, 0.f, 0.f};
    #pragma unroll 4
    for (int j = grp; j < deg; j += 4) {
        int c = __ldg(&seg[j]);
        uint4 w = __ldcg(reinterpret_cast<const uint4*>(g_Wth + (size_t)c * CHANNELS) + sub);
        const __half2* h = reinterpret_cast<const __half2*>(&w);
        #pragma unroll
        for (int k = 0; k < 4; k++) {
            float2 f = __half22float2(h[k]);
            acc[2 * k]     += f.x;
            acc[2 * k + 1] += f.y;
        }
    }
    // restore the zero-counts precondition for the next launch/replay
    if (valid && lane == 0) g_counts[raw] = 0;

    #pragma unroll
    for (int k = 0; k < 8; k++) {
        acc[k] += __shfl_down_sync(0xffffffffu, acc[k], 16);
        acc[k] += __shfl_down_sync(0xffffffffu, acc[k], 8);
    }
    if (grp == 0) {
        float4 b0 = __ldg(reinterpret_cast<const float4*>(b) + sub * 2);
        float4 b1 = __ldg(reinterpret_cast<const float4*>(b) + sub * 2 + 1);
        float4 o0 = make_float4(acc[0] + b0.x, acc[1] + b0.y, acc[2] + b0.z, acc[3] + b0.w);
        float4 o1 = make_float4(acc[4] + b1.x, acc[5] + b1.y, acc[6] + b1.z, acc[7] + b1.w);
        float4* dst = reinterpret_cast<float4*>(out + (size_t)warp * CHANNELS);
        __stcs(dst + sub * 2,     o0);
        __stcs(dst + sub * 2 + 1, o1);
    }
}

// ---------------------------------------------------------------------------
// 3) fixup (single block): fold overflow edges into out via vector reductions
//    (zero iterations on this dataset), then reset global state for the next
//    replay.
// ---------------------------------------------------------------------------
__global__ void fixup_kernel(float* __restrict__ out) {
    const int cnt  = g_ovf_cnt;
    const int rmin = g_row_min;
    long long total = (long long)cnt * 16;
    for (long long t = threadIdx.x; t < total; t += blockDim.x) {
        int e   = (int)(t >> 4);
        int sub = (int)(t & 15);
        int r = g_ovf_row[e] - rmin;
        int c = g_ovf_col[e];
        uint2 w = *reinterpret_cast<const uint2*>(g_Wth + (size_t)c * CHANNELS + sub * 4);
        float2 f0 = __half22float2(*reinterpret_cast<__half2*>(&w.x));
        float2 f1 = __half22float2(*reinterpret_cast<__half2*>(&w.y));
        float* dst = out + (size_t)r * CHANNELS + sub * 4;
        asm volatile("red.global.add.v4.f32 [%0], {%1, %2, %3, %4};"
                     :: "l"(dst), "f"(f0.x), "f"(f0.y), "f"(f1.x), "f"(f1.y)
                     : "memory");
    }
    __syncthreads();
    if (threadIdx.x == 0) {
        g_ovf_cnt = 0;
        g_row_min = INT_MAX;
    }
}

// ---------------------------------------------------------------------------
extern "C" void kernel_launch(void* const* d_in, const int* in_sizes, int n_in,
                              void* d_out, int out_size) {
    const void*  edge = d_in[0];
    const float* W    = (const float*)d_in[1];
    const float* b    = (const float*)d_in[2];
    float*       out  = (float*)d_out;

    const int E = in_sizes[0] / 2;
    const int C = in_sizes[2];             // 64
    const int N = in_sizes[1] / C;         // 100000

    // fused single-pass binning (+min, +dtype sniff) + W transpose, interleaved
    build_kernel<<<HBLOCKS + N / 32, 256>>>(W, edge, N, E);

    {   // gather: one warp per node (also resets counts)
        long long threads = (long long)N * 32;
        int blocks = (int)((threads + 255) / 256);
        gather_kernel<<<blocks, 256>>>(b, out, N);
    }

    fixup_kernel<<<1, 512>>>(out);   // overflow fold + state reset
}